// round 5
// baseline (speedup 1.0000x reference)
#include <cuda_runtime.h>
#include <cuda_fp16.h>
#include <cstdint>

// ---------------- problem constants ----------------
#define BB 4
#define TT 1024
#define DD 1024
#define HH 16
#define DK 64
#define DV 64
#define II 2816
#define ROWS (BB*TT)          // 4096

// ---------------- scratch (device globals; no runtime alloc) ----------------
__device__ float g_h1[ROWS*DD];
__device__ float g_qkv[(size_t)ROWS*3*DD];
__device__ float g_qc[ROWS*DD];
__device__ float g_kc[ROWS*DD];
__device__ float g_vc[ROWS*DD];
__device__ float g_hb[ROWS*HH];
__device__ float g_ha[ROWS*HH];
__device__ float g_beta[ROWS*HH];
__device__ float g_gex[ROWS*HH];
__device__ float g_o [ROWS*DD];
__device__ float g_h2[ROWS*DD];
__device__ float g_gml[(size_t)ROWS*2*II];
__device__ float g_sdump[BB*HH*DK*DV];
__device__ __half g_A2[(size_t)ROWS*2*II];       // [hi|lo] rows, max KX=5632
__device__ __half g_B2[(size_t)(2*II)*DD];       // single-copy [N,K] fp16 weights

// ================= helpers =================
__device__ __forceinline__ uint32_t smem_u32(const void* p) {
    uint32_t a;
    asm("{ .reg .u64 t; cvta.to.shared.u64 t, %1; cvt.u32.u64 %0, t; }" : "=r"(a) : "l"(p));
    return a;
}
__device__ __forceinline__ void cp16(uint32_t dst, const void* src) {
    asm volatile("cp.async.cg.shared.global [%0], [%1], 16;" :: "r"(dst), "l"(src) : "memory");
}
__device__ __forceinline__ void ldm_x4(uint32_t* r, uint32_t a) {
    asm volatile("ldmatrix.sync.aligned.m8n8.x4.shared.b16 {%0,%1,%2,%3}, [%4];"
                 : "=r"(r[0]), "=r"(r[1]), "=r"(r[2]), "=r"(r[3]) : "r"(a));
}
__device__ __forceinline__ void mma_f16(float* c, const uint32_t* a, const uint32_t* b) {
    asm volatile(
        "mma.sync.aligned.m16n8k16.row.col.f32.f16.f16.f32 "
        "{%0,%1,%2,%3}, {%4,%5,%6,%7}, {%8,%9}, {%0,%1,%2,%3};"
        : "+f"(c[0]), "+f"(c[1]), "+f"(c[2]), "+f"(c[3])
        : "r"(a[0]), "r"(a[1]), "r"(a[2]), "r"(a[3]), "r"(b[0]), "r"(b[1]));
}
__device__ __forceinline__ void split2(float x, __half& hi, __half& lo) {
    hi = __float2half_rn(x);
    lo = __float2half_rn(x - __half2float(hi));
}

// ================= fp16 HMMA GEMM =================
// C[4096,Nfull] = A2[M, 2*KB] * Bw[N, KB]^T (+Add), where A2 rows = [hi | lo]
// and the B k-index wraps mod KB (second half of extended K reuses B).
// CTA tile 128(M) x 256(N), 256 threads = 8 warps (2x4 of 64x64), BK=64, 3-stage cp.async.
#define STG_BYTES 49152                 // 16KB A + 32KB B per stage
#define GSMEM (3*STG_BYTES)             // 144 KB

__global__ void __launch_bounds__(256, 1)
tc_gemm(const __half* __restrict__ A, const __half* __restrict__ B,
        const float* __restrict__ Add, float* __restrict__ C, int Nfull, int KB)
{
    extern __shared__ __align__(1024) char smem[];
    uint32_t sb = smem_u32(smem);
    const int tid = threadIdx.x;
    const int lane = tid & 31, w = tid >> 5;
    const int wm = w & 1, wn = w >> 1;          // 2 x 4 warp grid
    const int m0 = blockIdx.y * 128, n0 = blockIdx.x * 256;
    const int KX = 2 * KB;
    const int NK = KX >> 6;

    const __half* Ab = A + (size_t)m0 * KX;
    const __half* Bb = B + (size_t)n0 * KB;

    const int cr = tid >> 3, cc = tid & 7;      // cr 0..31
    const uint32_t cdst = (uint32_t)(cr * 128 + ((cc ^ (cr & 7)) << 4));

    float acc[4][8][4];
    #pragma unroll
    for (int i = 0; i < 4; i++)
        #pragma unroll
        for (int j = 0; j < 8; j++)
            #pragma unroll
            for (int l = 0; l < 4; l++) acc[i][j][l] = 0.f;

    const int rowA = wm * 64 + (lane & 15);
    const int rowB = wn * 64 + (lane & 7) + ((lane >> 4) << 3);
    uint32_t aChunk[4], bChunk[4];
    #pragma unroll
    for (int ks = 0; ks < 4; ks++) {
        aChunk[ks] = (uint32_t)(((ks * 2 + (lane >> 4)) ^ (rowA & 7)) << 4);
        bChunk[ks] = (uint32_t)(((ks * 2 + ((lane >> 3) & 1)) ^ (rowB & 7)) << 4);
    }

    #define LOAD_STAGE(kt, s) {                                                   \
        uint32_t sa = sb + (s) * STG_BYTES, sbB = sa + 16384;                      \
        int kA = (kt) * 64;                                                        \
        int kB = (kA >= KB) ? kA - KB : kA;                                        \
        const __half* Asrc = Ab + (size_t)cr * KX + kA + cc * 8;                   \
        const __half* Bsrc = Bb + (size_t)cr * KB + kB + cc * 8;                   \
        _Pragma("unroll")                                                          \
        for (int t = 0; t < 4; t++)                                                \
            cp16(sa + cdst + t * 4096, Asrc + (size_t)(t * 32) * KX);              \
        _Pragma("unroll")                                                          \
        for (int t = 0; t < 8; t++)                                                \
            cp16(sbB + cdst + t * 4096, Bsrc + (size_t)(t * 32) * KB);             \
        asm volatile("cp.async.commit_group;" ::: "memory");                       \
    }

    LOAD_STAGE(0, 0);
    LOAD_STAGE(1, 1);

    for (int kt = 0; kt < NK; kt++) {
        int s = kt - (kt / 3) * 3;
        asm volatile("cp.async.wait_group 1;" ::: "memory");
        __syncthreads();
        if (kt + 2 < NK) {
            int s2 = (kt + 2) - ((kt + 2) / 3) * 3;
            LOAD_STAGE(kt + 2, s2);
        } else {
            asm volatile("cp.async.commit_group;" ::: "memory");
        }
        uint32_t sa = sb + s * STG_BYTES, sbB = sa + 16384;
        uint32_t baseA = sa + (uint32_t)rowA * 128;
        uint32_t baseB = sbB + (uint32_t)rowB * 128;
        #pragma unroll
        for (int ks = 0; ks < 4; ks++) {
            uint32_t a[4][4], b[8][2];
            #pragma unroll
            for (int mt = 0; mt < 4; mt++)
                ldm_x4(a[mt], baseA + mt * 2048 + aChunk[ks]);
            #pragma unroll
            for (int np = 0; np < 4; np++) {
                uint32_t r[4];
                ldm_x4(r, baseB + np * 2048 + bChunk[ks]);
                b[2*np][0] = r[0]; b[2*np][1] = r[1];
                b[2*np+1][0] = r[2]; b[2*np+1][1] = r[3];
            }
            #pragma unroll
            for (int mt = 0; mt < 4; mt++)
                #pragma unroll
                for (int nt = 0; nt < 8; nt++)
                    mma_f16(acc[mt][nt], a[mt], b[nt]);
        }
        __syncthreads();
    }

    // ---- epilogue ----
    const int l4 = lane >> 2, l2 = (lane & 3) * 2;
    #pragma unroll
    for (int mt = 0; mt < 4; mt++) {
        size_t r0 = (size_t)(m0 + wm * 64 + mt * 16 + l4);
        #pragma unroll
        for (int nt = 0; nt < 8; nt++) {
            size_t cidx = r0 * Nfull + (n0 + wn * 64 + nt * 8 + l2);
            float2 v0 = make_float2(acc[mt][nt][0], acc[mt][nt][1]);
            float2 v1 = make_float2(acc[mt][nt][2], acc[mt][nt][3]);
            if (Add) {
                float2 a0 = *(const float2*)(Add + cidx);
                float2 a1 = *(const float2*)(Add + cidx + 8 * Nfull);
                v0.x += a0.x; v0.y += a0.y; v1.x += a1.x; v1.y += a1.y;
            }
            *(float2*)(C + cidx) = v0;
            *(float2*)(C + cidx + 8 * Nfull) = v1;
        }
    }
}

// ================= fused norm + fp16 split (A-operand) =================
__global__ __launch_bounds__(256) void rmsnorm_splitA(
    const float* __restrict__ in, const float* __restrict__ w,
    float* __restrict__ hout, __half* __restrict__ A2)
{
    int row = blockIdx.x;
    __shared__ float red[8];
    const float* p = in + (size_t)row * DD;
    float v0 = p[threadIdx.x];
    float v1 = p[threadIdx.x + 256];
    float v2 = p[threadIdx.x + 512];
    float v3 = p[threadIdx.x + 768];
    float ss = v0*v0 + v1*v1 + v2*v2 + v3*v3;
    #pragma unroll
    for (int off = 16; off; off >>= 1) ss += __shfl_xor_sync(0xffffffffu, ss, off);
    if ((threadIdx.x & 31) == 0) red[threadIdx.x >> 5] = ss;
    __syncthreads();
    float tot = 0.f;
    #pragma unroll
    for (int i = 0; i < 8; i++) tot += red[i];
    float r = rsqrtf(tot * (1.0f/1024.0f) + 1e-6f);
    __half* a = A2 + (size_t)row * 2048;
    float* q = hout ? hout + (size_t)row * DD : nullptr;
    float vals[4] = {v0, v1, v2, v3};
    #pragma unroll
    for (int i = 0; i < 4; i++) {
        int c = threadIdx.x + i * 256;
        float val = vals[i] * r * w[c];
        if (q) q[c] = val;
        __half hi, lo; split2(val, hi, lo);
        a[c] = hi; a[1024 + c] = lo;
    }
}

__global__ __launch_bounds__(256) void ornorm_splitA(
    const float* __restrict__ o, const float* __restrict__ w, __half* __restrict__ A2)
{
    int row = blockIdx.x, t = threadIdx.x;
    float4 vv = *(const float4*)(o + (size_t)row * 1024 + t * 4);
    float ss = vv.x*vv.x + vv.y*vv.y + vv.z*vv.z + vv.w*vv.w;
    ss += __shfl_xor_sync(0xffffffffu, ss, 1);
    ss += __shfl_xor_sync(0xffffffffu, ss, 2);
    ss += __shfl_xor_sync(0xffffffffu, ss, 4);
    ss += __shfl_xor_sync(0xffffffffu, ss, 8);
    float r = rsqrtf(ss * (1.0f/64.0f) + 1e-6f);
    __half* a = A2 + (size_t)row * 2048;
    float vals[4] = {vv.x, vv.y, vv.z, vv.w};
    #pragma unroll
    for (int j = 0; j < 4; j++) {
        int c = t * 4 + j;
        float val = vals[j] * r * w[c & 63];
        __half hi, lo; split2(val, hi, lo);
        a[c] = hi; a[1024 + c] = lo;
    }
}

__global__ __launch_bounds__(256) void swiglu_splitA(
    const float* __restrict__ gml, __half* __restrict__ A2)
{
    int col = blockIdx.x * 256 + threadIdx.x;
    int row = blockIdx.y;
    float g = gml[(size_t)row * 5632 + col];
    float y = gml[(size_t)row * 5632 + 2816 + col];
    float m = g / (1.f + expf(-g)) * y;
    __half hi, lo; split2(m, hi, lo);
    A2[(size_t)row * 5632 + col] = hi;
    A2[(size_t)row * 5632 + 2816 + col] = lo;
}

// W[K,N] -> B2[nOff+n][k] fp16 (transposed, single copy)
__global__ __launch_bounds__(256) void convB_kernel(
    const float* __restrict__ W, __half* __restrict__ B2,
    int K, int N, int nOff)
{
    __shared__ float tile[32][33];
    int k0 = blockIdx.y * 32, n0 = blockIdx.x * 32;
    int tx = threadIdx.x & 31, ty = threadIdx.x >> 5;
    for (int i = ty; i < 32; i += 8)
        tile[i][tx] = W[(size_t)(k0 + i) * N + n0 + tx];
    __syncthreads();
    for (int i = ty; i < 32; i += 8) {
        size_t rb = (size_t)(nOff + n0 + i) * K;
        B2[rb + k0 + tx] = __float2half_rn(tile[tx][i]);
    }
}

// ---------------- small projections ----------------
__global__ __launch_bounds__(256) void proj_ba_kernel(
    const float* __restrict__ h, const float* __restrict__ Wb, const float* __restrict__ Wa,
    float* __restrict__ hb, float* __restrict__ ha)
{
    int row = blockIdx.x;
    __shared__ float sh[1024];
    for (int i = threadIdx.x; i < 1024; i += 256) sh[i] = h[(size_t)row * DD + i];
    __syncthreads();
    int grp = threadIdx.x >> 3, l = threadIdx.x & 7;
    const float* W = (grp < 16) ? Wb : Wa;
    int col = grp & 15;
    float s = 0.f;
    for (int k = l; k < 1024; k += 8) s += sh[k] * W[k * HH + col];
    s += __shfl_xor_sync(0xffffffffu, s, 1);
    s += __shfl_xor_sync(0xffffffffu, s, 2);
    s += __shfl_xor_sync(0xffffffffu, s, 4);
    if (l == 0) {
        if (grp < 16) hb[(size_t)row * HH + col] = s;
        else          ha[(size_t)row * HH + col] = s;
    }
}

// ---------------- causal depthwise conv (K=4) + SiLU, strided input ----------------
__global__ __launch_bounds__(256) void conv_silu_kernel(
    const float* __restrict__ in, int inStride, int inOff,
    float* __restrict__ out, const float* __restrict__ w)
{
    int idx = blockIdx.x * 256 + threadIdx.x;
    int c   = idx & 1023;
    int tch = (idx >> 10) & 15;
    int b   = idx >> 14;
    int t0  = tch * 64;
    float w0 = w[c*4+0], w1 = w[c*4+1], w2 = w[c*4+2], w3 = w[c*4+3];
    size_t ibase = ((size_t)b * TT) * inStride + inOff + c;
    size_t obase = ((size_t)b * TT) * DD + c;
    float xm3 = (t0 >= 3) ? in[ibase + (size_t)(t0-3)*inStride] : 0.f;
    float xm2 = (t0 >= 2) ? in[ibase + (size_t)(t0-2)*inStride] : 0.f;
    float xm1 = (t0 >= 1) ? in[ibase + (size_t)(t0-1)*inStride] : 0.f;
    #pragma unroll 8
    for (int j = 0; j < 64; j++) {
        float xt = in[ibase + (size_t)(t0+j)*inStride];
        float s  = xm3*w0 + xm2*w1 + xm1*w2 + xt*w3;
        out[obase + (size_t)(t0+j)*DD] = s / (1.f + expf(-s));
        xm3 = xm2; xm2 = xm1; xm1 = xt;
    }
}

// ---------------- L2 norm of q (with scale) and k ----------------
__global__ __launch_bounds__(256) void l2norm_qk_kernel(
    float* __restrict__ qc, float* __restrict__ kc)
{
    int gw = blockIdx.x * 8 + (threadIdx.x >> 5);
    int lane = threadIdx.x & 31;
    float* arr = (gw < 65536) ? qc : kc;
    size_t base = (size_t)(gw & 65535) * 64;
    float a = arr[base + lane], b = arr[base + 32 + lane];
    float ss = a*a + b*b;
    #pragma unroll
    for (int off = 16; off; off >>= 1) ss += __shfl_xor_sync(0xffffffffu, ss, off);
    float r = rsqrtf(ss + 1e-6f);
    if (gw < 65536) r *= 0.125f;
    arr[base + lane]      = a * r;
    arr[base + 32 + lane] = b * r;
}

// ---------------- beta / gate ----------------
__global__ __launch_bounds__(256) void betag_kernel(
    const float* __restrict__ hb, const float* __restrict__ ha,
    const float* __restrict__ dtb, const float* __restrict__ Alog,
    float* __restrict__ beta, float* __restrict__ gex)
{
    int idx = blockIdx.x * 256 + threadIdx.x;
    int hh = idx & 15;
    beta[idx] = 2.f / (1.f + expf(-hb[idx]));
    float xv = ha[idx] + dtb[hh];
    float sp = (xv > 20.f) ? xv : log1pf(expf(xv));
    gex[idx] = expf(-expf(Alog[hh]) * sp);
}

// ---------------- gated delta-rule scan (8-step staging) ----------------
__global__ __launch_bounds__(256) void scan_kernel(
    const float* __restrict__ q, const float* __restrict__ k, const float* __restrict__ v,
    const float* __restrict__ beta, const float* __restrict__ gex,
    float* __restrict__ o, float* __restrict__ state)
{
    int hf   = blockIdx.x & 1;
    int h    = (blockIdx.x >> 1) & 15;
    int b    = blockIdx.x >> 5;
    int tid  = threadIdx.x, lane = tid & 31, w = tid >> 5;
    int dvL  = (w << 2) | (lane & 3);
    int dv   = hf * 32 + dvL;
    int kbase = (lane >> 2) << 3;

    __shared__ float sQ[2][8][64], sK[2][8][64], sV[2][8][32], sBe[2][8], sG[2][8];

    float S[8];
    #pragma unroll
    for (int j = 0; j < 8; j++) S[j] = 0.f;

    size_t chan = (size_t)h * 64;

    #define SCAN_LOAD(st, bf) {                                                          \
        size_t tb = (size_t)b * TT + (st) * 8;                                           \
        for (int i = tid; i < 1296; i += 256) {                                          \
            if (i < 512)       sQ[bf][i>>6][i&63] = q[(tb + (i>>6))*DD + chan + (i&63)]; \
            else if (i < 1024) { int j2 = i-512;                                         \
                sK[bf][j2>>6][j2&63] = k[(tb + (j2>>6))*DD + chan + (j2&63)]; }          \
            else if (i < 1280) { int j2 = i-1024;                                        \
                sV[bf][j2>>5][j2&31] = v[(tb + (j2>>5))*DD + chan + hf*32 + (j2&31)]; }  \
            else { int j2 = i-1280;                                                      \
                if (j2 < 8) sBe[bf][j2] = beta[(tb + j2)*HH + h];                        \
                else        sG[bf][j2-8] = gex[(tb + j2-8)*HH + h]; }                    \
        }                                                                                \
    }

    SCAN_LOAD(0, 0);

    for (int st = 0; st < 128; st++) {
        int buf = st & 1;
        __syncthreads();
        if (st + 1 < 128) SCAN_LOAD(st + 1, buf ^ 1);
        #pragma unroll 2
        for (int tt = 0; tt < 8; tt++) {
            float ge = sG[buf][tt], bt = sBe[buf][tt];
            float kv = 0.f;
            #pragma unroll
            for (int j = 0; j < 8; j++) { S[j] *= ge; kv = fmaf(sK[buf][tt][kbase+j], S[j], kv); }
            kv += __shfl_xor_sync(0xffffffffu, kv, 4);
            kv += __shfl_xor_sync(0xffffffffu, kv, 8);
            kv += __shfl_xor_sync(0xffffffffu, kv, 16);
            float delta = (sV[buf][tt][dvL] - kv) * bt;
            float ov = 0.f;
            #pragma unroll
            for (int j = 0; j < 8; j++) {
                S[j] = fmaf(sK[buf][tt][kbase+j], delta, S[j]);
                ov   = fmaf(sQ[buf][tt][kbase+j], S[j], ov);
            }
            ov += __shfl_xor_sync(0xffffffffu, ov, 4);
            ov += __shfl_xor_sync(0xffffffffu, ov, 8);
            ov += __shfl_xor_sync(0xffffffffu, ov, 16);
            if ((lane >> 2) == 0)
                o[((size_t)b * TT + st * 8 + tt) * DD + chan + dv] = ov;
        }
    }
    #pragma unroll
    for (int j = 0; j < 8; j++)
        state[(((size_t)b * HH + h) * DK + kbase + j) * DV + dv] = S[j];
}

// ---------------- host launch ----------------
extern "C" void kernel_launch(void* const* d_in, const int* in_sizes, int n_in,
                              void* d_out, int out_size)
{
    const float* x    = (const float*)d_in[0];
    const float* anw  = (const float*)d_in[1];
    const float* Wq   = (const float*)d_in[2];
    const float* Wk   = (const float*)d_in[3];
    const float* Wv   = (const float*)d_in[4];
    const float* cq   = (const float*)d_in[5];
    const float* ck   = (const float*)d_in[6];
    const float* cv   = (const float*)d_in[7];
    const float* Wb   = (const float*)d_in[8];
    const float* Wa   = (const float*)d_in[9];
    const float* dtb  = (const float*)d_in[10];
    const float* Alog = (const float*)d_in[11];
    const float* ow   = (const float*)d_in[12];
    const float* Wo   = (const float*)d_in[13];
    const float* mlpw = (const float*)d_in[14];
    const float* Wg   = (const float*)d_in[15];
    const float* Wd   = (const float*)d_in[16];
    float* out = (float*)d_out;

    float *h1,*qkv,*qc,*kc,*vc,*hb,*ha,*beta,*gex,*o,*h2,*gml,*sdump;
    __half *A2, *B2;
    cudaGetSymbolAddress((void**)&h1, g_h1);
    cudaGetSymbolAddress((void**)&qkv, g_qkv);
    cudaGetSymbolAddress((void**)&qc, g_qc);
    cudaGetSymbolAddress((void**)&kc, g_kc);
    cudaGetSymbolAddress((void**)&vc, g_vc);
    cudaGetSymbolAddress((void**)&hb, g_hb);
    cudaGetSymbolAddress((void**)&ha, g_ha);
    cudaGetSymbolAddress((void**)&beta, g_beta);
    cudaGetSymbolAddress((void**)&gex,  g_gex);
    cudaGetSymbolAddress((void**)&o,  g_o);
    cudaGetSymbolAddress((void**)&h2, g_h2);
    cudaGetSymbolAddress((void**)&gml, g_gml);
    cudaGetSymbolAddress((void**)&sdump, g_sdump);
    cudaGetSymbolAddress((void**)&A2, g_A2);
    cudaGetSymbolAddress((void**)&B2, g_B2);

    cudaFuncSetAttribute(tc_gemm, cudaFuncAttributeMaxDynamicSharedMemorySize, GSMEM);

    float* state_out = (out_size >= ROWS*DD + BB*HH*DK*DV) ? (out + (size_t)ROWS*DD) : sdump;

    // 1) pre-attn norm fused with fp16 split (keeps fp32 h1 for proj_ba)
    rmsnorm_splitA<<<ROWS, 256>>>(x, anw, h1, A2);
    // 2) fused QKV GEMM: N=3072, KB=1024
    convB_kernel<<<dim3(32, 32), 256>>>(Wq, B2, 1024, 1024, 0);
    convB_kernel<<<dim3(32, 32), 256>>>(Wk, B2, 1024, 1024, 1024);
    convB_kernel<<<dim3(32, 32), 256>>>(Wv, B2, 1024, 1024, 2048);
    tc_gemm<<<dim3(12, 32), 256, GSMEM>>>(A2, B2, nullptr, qkv, 3072, 1024);
    // 3) conv + silu, projections
    conv_silu_kernel<<<256, 256>>>(qkv, 3072, 0,    qc, cq);
    conv_silu_kernel<<<256, 256>>>(qkv, 3072, 1024, kc, ck);
    conv_silu_kernel<<<256, 256>>>(qkv, 3072, 2048, vc, cv);
    proj_ba_kernel<<<ROWS, 256>>>(h1, Wb, Wa, hb, ha);
    l2norm_qk_kernel<<<16384, 256>>>(qc, kc);
    betag_kernel<<<256, 256>>>(hb, ha, dtb, Alog, beta, gex);
    // 4) sequential delta-rule scan
    scan_kernel<<<128, 256>>>(qc, kc, vc, beta, gex, o, state_out);
    // 5) per-head norm fused with split; h2 = x + o' @ Wo
    ornorm_splitA<<<ROWS, 256>>>(o, ow, A2);
    convB_kernel<<<dim3(32, 32), 256>>>(Wo, B2, 1024, 1024, 0);
    tc_gemm<<<dim3(4, 32), 256, GSMEM>>>(A2, B2, x, h2, 1024, 1024);
    // 6) MLP
    rmsnorm_splitA<<<ROWS, 256>>>(h2, mlpw, nullptr, A2);
    convB_kernel<<<dim3(176, 32), 256>>>(Wg, B2, 1024, 5632, 0);
    tc_gemm<<<dim3(22, 32), 256, GSMEM>>>(A2, B2, nullptr, gml, 5632, 1024);
    swiglu_splitA<<<dim3(11, ROWS), 256>>>(gml, A2);
    convB_kernel<<<dim3(32, 88), 256>>>(Wd, B2, 2816, 1024, 0);
    tc_gemm<<<dim3(4, 32), 256, GSMEM>>>(A2, B2, h2, out, 1024, 2816);
}

// round 6
// speedup vs baseline: 1.0028x; 1.0028x over previous
#include <cuda_runtime.h>
#include <cuda_fp16.h>
#include <cstdint>

// ---------------- problem constants ----------------
#define BB 4
#define TT 1024
#define DD 1024
#define HH 16
#define DK 64
#define DV 64
#define II 2816
#define ROWS (BB*TT)          // 4096

// ---------------- scratch (device globals; no runtime alloc) ----------------
__device__ float g_h1[ROWS*DD];
__device__ float g_qkv[(size_t)ROWS*3*DD];
__device__ float g_qc[ROWS*DD];
__device__ float g_kc[ROWS*DD];
__device__ float g_vc[ROWS*DD];
__device__ float g_hb[ROWS*HH];
__device__ float g_ha[ROWS*HH];
__device__ float g_beta[ROWS*HH];
__device__ float g_gex[ROWS*HH];
__device__ float g_o [ROWS*DD];
__device__ float g_h2[ROWS*DD];
__device__ float g_gml[(size_t)ROWS*2*II];
__device__ float g_sdump[BB*HH*DK*DV];
__device__ __half g_A2[(size_t)ROWS*2*II];       // [hi|lo] rows, max KX=5632
__device__ __half g_B2[(size_t)(2*II)*DD];       // single-copy [N,K] fp16 weights

// ================= helpers =================
__device__ __forceinline__ uint32_t smem_u32(const void* p) {
    uint32_t a;
    asm("{ .reg .u64 t; cvta.to.shared.u64 t, %1; cvt.u32.u64 %0, t; }" : "=r"(a) : "l"(p));
    return a;
}
__device__ __forceinline__ void cp16(uint32_t dst, const void* src) {
    asm volatile("cp.async.cg.shared.global [%0], [%1], 16;" :: "r"(dst), "l"(src) : "memory");
}
__device__ __forceinline__ void ldm_x4(uint32_t* r, uint32_t a) {
    asm volatile("ldmatrix.sync.aligned.m8n8.x4.shared.b16 {%0,%1,%2,%3}, [%4];"
                 : "=r"(r[0]), "=r"(r[1]), "=r"(r[2]), "=r"(r[3]) : "r"(a));
}
__device__ __forceinline__ void mma_f16(float* c, const uint32_t* a, const uint32_t* b) {
    asm volatile(
        "mma.sync.aligned.m16n8k16.row.col.f32.f16.f16.f32 "
        "{%0,%1,%2,%3}, {%4,%5,%6,%7}, {%8,%9}, {%0,%1,%2,%3};"
        : "+f"(c[0]), "+f"(c[1]), "+f"(c[2]), "+f"(c[3])
        : "r"(a[0]), "r"(a[1]), "r"(a[2]), "r"(a[3]), "r"(b[0]), "r"(b[1]));
}
__device__ __forceinline__ void split2(float x, __half& hi, __half& lo) {
    hi = __float2half_rn(x);
    lo = __float2half_rn(x - __half2float(hi));
}

// ================= fp16 HMMA GEMM =================
// C[4096,Nfull] = A2[M, 2*KB] * Bw[N, KB]^T (+Add), where A2 rows = [hi | lo]
// and the B k-index wraps mod KB (second half of extended K reuses B).
// CTA tile 128(M) x 256(N), 256 threads = 8 warps (2x4 of 64x64), BK=64, 3-stage cp.async.
#define STG_BYTES 49152                 // 16KB A + 32KB B per stage
#define GSMEM (3*STG_BYTES)             // 144 KB

__global__ void __launch_bounds__(256, 1)
tc_gemm(const __half* __restrict__ A, const __half* __restrict__ B,
        const float* __restrict__ Add, float* __restrict__ C, int Nfull, int KB)
{
    extern __shared__ __align__(1024) char smem[];
    uint32_t sb = smem_u32(smem);
    const int tid = threadIdx.x;
    const int lane = tid & 31, w = tid >> 5;
    const int wm = w & 1, wn = w >> 1;          // 2 x 4 warp grid
    const int m0 = blockIdx.y * 128, n0 = blockIdx.x * 256;
    const int KX = 2 * KB;
    const int NK = KX >> 6;

    const __half* Ab = A + (size_t)m0 * KX;
    const __half* Bb = B + (size_t)n0 * KB;

    const int cr = tid >> 3, cc = tid & 7;      // cr 0..31
    const uint32_t cdst = (uint32_t)(cr * 128 + ((cc ^ (cr & 7)) << 4));

    float acc[4][8][4];
    #pragma unroll
    for (int i = 0; i < 4; i++)
        #pragma unroll
        for (int j = 0; j < 8; j++)
            #pragma unroll
            for (int l = 0; l < 4; l++) acc[i][j][l] = 0.f;

    const int rowA = wm * 64 + (lane & 15);
    const int rowB = wn * 64 + (lane & 7) + ((lane >> 4) << 3);
    uint32_t aChunk[4], bChunk[4];
    #pragma unroll
    for (int ks = 0; ks < 4; ks++) {
        aChunk[ks] = (uint32_t)(((ks * 2 + (lane >> 4)) ^ (rowA & 7)) << 4);
        bChunk[ks] = (uint32_t)(((ks * 2 + ((lane >> 3) & 1)) ^ (rowB & 7)) << 4);
    }

    #define LOAD_STAGE(kt, s) {                                                   \
        uint32_t sa = sb + (s) * STG_BYTES, sbB = sa + 16384;                      \
        int kA = (kt) * 64;                                                        \
        int kB = (kA >= KB) ? kA - KB : kA;                                        \
        const __half* Asrc = Ab + (size_t)cr * KX + kA + cc * 8;                   \
        const __half* Bsrc = Bb + (size_t)cr * KB + kB + cc * 8;                   \
        _Pragma("unroll")                                                          \
        for (int t = 0; t < 4; t++)                                                \
            cp16(sa + cdst + t * 4096, Asrc + (size_t)(t * 32) * KX);              \
        _Pragma("unroll")                                                          \
        for (int t = 0; t < 8; t++)                                                \
            cp16(sbB + cdst + t * 4096, Bsrc + (size_t)(t * 32) * KB);             \
        asm volatile("cp.async.commit_group;" ::: "memory");                       \
    }

    LOAD_STAGE(0, 0);
    LOAD_STAGE(1, 1);

    for (int kt = 0; kt < NK; kt++) {
        int s = kt - (kt / 3) * 3;
        asm volatile("cp.async.wait_group 1;" ::: "memory");
        __syncthreads();
        if (kt + 2 < NK) {
            int s2 = (kt + 2) - ((kt + 2) / 3) * 3;
            LOAD_STAGE(kt + 2, s2);
        } else {
            asm volatile("cp.async.commit_group;" ::: "memory");
        }
        uint32_t sa = sb + s * STG_BYTES, sbB = sa + 16384;
        uint32_t baseA = sa + (uint32_t)rowA * 128;
        uint32_t baseB = sbB + (uint32_t)rowB * 128;
        #pragma unroll
        for (int ks = 0; ks < 4; ks++) {
            uint32_t a[4][4], b[8][2];
            #pragma unroll
            for (int mt = 0; mt < 4; mt++)
                ldm_x4(a[mt], baseA + mt * 2048 + aChunk[ks]);
            #pragma unroll
            for (int np = 0; np < 4; np++) {
                uint32_t r[4];
                ldm_x4(r, baseB + np * 2048 + bChunk[ks]);
                b[2*np][0] = r[0]; b[2*np][1] = r[1];
                b[2*np+1][0] = r[2]; b[2*np+1][1] = r[3];
            }
            #pragma unroll
            for (int mt = 0; mt < 4; mt++)
                #pragma unroll
                for (int nt = 0; nt < 8; nt++)
                    mma_f16(acc[mt][nt], a[mt], b[nt]);
        }
        __syncthreads();
    }

    // ---- epilogue ----
    const int l4 = lane >> 2, l2 = (lane & 3) * 2;
    #pragma unroll
    for (int mt = 0; mt < 4; mt++) {
        size_t r0 = (size_t)(m0 + wm * 64 + mt * 16 + l4);
        #pragma unroll
        for (int nt = 0; nt < 8; nt++) {
            size_t cidx = r0 * Nfull + (n0 + wn * 64 + nt * 8 + l2);
            float2 v0 = make_float2(acc[mt][nt][0], acc[mt][nt][1]);
            float2 v1 = make_float2(acc[mt][nt][2], acc[mt][nt][3]);
            if (Add) {
                float2 a0 = *(const float2*)(Add + cidx);
                float2 a1 = *(const float2*)(Add + cidx + 8 * Nfull);
                v0.x += a0.x; v0.y += a0.y; v1.x += a1.x; v1.y += a1.y;
            }
            *(float2*)(C + cidx) = v0;
            *(float2*)(C + cidx + 8 * Nfull) = v1;
        }
    }
}

// ================= fused norm + fp16 split (A-operand) =================
__global__ __launch_bounds__(256) void rmsnorm_splitA(
    const float* __restrict__ in, const float* __restrict__ w,
    float* __restrict__ hout, __half* __restrict__ A2)
{
    int row = blockIdx.x;
    __shared__ float red[8];
    const float* p = in + (size_t)row * DD;
    float v0 = p[threadIdx.x];
    float v1 = p[threadIdx.x + 256];
    float v2 = p[threadIdx.x + 512];
    float v3 = p[threadIdx.x + 768];
    float ss = v0*v0 + v1*v1 + v2*v2 + v3*v3;
    #pragma unroll
    for (int off = 16; off; off >>= 1) ss += __shfl_xor_sync(0xffffffffu, ss, off);
    if ((threadIdx.x & 31) == 0) red[threadIdx.x >> 5] = ss;
    __syncthreads();
    float tot = 0.f;
    #pragma unroll
    for (int i = 0; i < 8; i++) tot += red[i];
    float r = rsqrtf(tot * (1.0f/1024.0f) + 1e-6f);
    __half* a = A2 + (size_t)row * 2048;
    float* q = hout ? hout + (size_t)row * DD : nullptr;
    float vals[4] = {v0, v1, v2, v3};
    #pragma unroll
    for (int i = 0; i < 4; i++) {
        int c = threadIdx.x + i * 256;
        float val = vals[i] * r * w[c];
        if (q) q[c] = val;
        __half hi, lo; split2(val, hi, lo);
        a[c] = hi; a[1024 + c] = lo;
    }
}

__global__ __launch_bounds__(256) void ornorm_splitA(
    const float* __restrict__ o, const float* __restrict__ w, __half* __restrict__ A2)
{
    int row = blockIdx.x, t = threadIdx.x;
    float4 vv = *(const float4*)(o + (size_t)row * 1024 + t * 4);
    float ss = vv.x*vv.x + vv.y*vv.y + vv.z*vv.z + vv.w*vv.w;
    ss += __shfl_xor_sync(0xffffffffu, ss, 1);
    ss += __shfl_xor_sync(0xffffffffu, ss, 2);
    ss += __shfl_xor_sync(0xffffffffu, ss, 4);
    ss += __shfl_xor_sync(0xffffffffu, ss, 8);
    float r = rsqrtf(ss * (1.0f/64.0f) + 1e-6f);
    __half* a = A2 + (size_t)row * 2048;
    float vals[4] = {vv.x, vv.y, vv.z, vv.w};
    #pragma unroll
    for (int j = 0; j < 4; j++) {
        int c = t * 4 + j;
        float val = vals[j] * r * w[c & 63];
        __half hi, lo; split2(val, hi, lo);
        a[c] = hi; a[1024 + c] = lo;
    }
}

__global__ __launch_bounds__(256) void swiglu_splitA(
    const float* __restrict__ gml, __half* __restrict__ A2)
{
    int col = blockIdx.x * 256 + threadIdx.x;
    int row = blockIdx.y;
    float g = gml[(size_t)row * 5632 + col];
    float y = gml[(size_t)row * 5632 + 2816 + col];
    float m = g / (1.f + expf(-g)) * y;
    __half hi, lo; split2(m, hi, lo);
    A2[(size_t)row * 5632 + col] = hi;
    A2[(size_t)row * 5632 + 2816 + col] = lo;
}

// W[K,N] -> B2[nOff+n][k] fp16 (transposed, single copy)
__global__ __launch_bounds__(256) void convB_kernel(
    const float* __restrict__ W, __half* __restrict__ B2,
    int K, int N, int nOff)
{
    __shared__ float tile[32][33];
    int k0 = blockIdx.y * 32, n0 = blockIdx.x * 32;
    int tx = threadIdx.x & 31, ty = threadIdx.x >> 5;
    for (int i = ty; i < 32; i += 8)
        tile[i][tx] = W[(size_t)(k0 + i) * N + n0 + tx];
    __syncthreads();
    for (int i = ty; i < 32; i += 8) {
        size_t rb = (size_t)(nOff + n0 + i) * K;
        B2[rb + k0 + tx] = __float2half_rn(tile[tx][i]);
    }
}

// ---------------- small projections ----------------
__global__ __launch_bounds__(256) void proj_ba_kernel(
    const float* __restrict__ h, const float* __restrict__ Wb, const float* __restrict__ Wa,
    float* __restrict__ hb, float* __restrict__ ha)
{
    int row = blockIdx.x;
    __shared__ float sh[1024];
    for (int i = threadIdx.x; i < 1024; i += 256) sh[i] = h[(size_t)row * DD + i];
    __syncthreads();
    int grp = threadIdx.x >> 3, l = threadIdx.x & 7;
    const float* W = (grp < 16) ? Wb : Wa;
    int col = grp & 15;
    float s = 0.f;
    for (int k = l; k < 1024; k += 8) s += sh[k] * W[k * HH + col];
    s += __shfl_xor_sync(0xffffffffu, s, 1);
    s += __shfl_xor_sync(0xffffffffu, s, 2);
    s += __shfl_xor_sync(0xffffffffu, s, 4);
    if (l == 0) {
        if (grp < 16) hb[(size_t)row * HH + col] = s;
        else          ha[(size_t)row * HH + col] = s;
    }
}

// ---------------- causal depthwise conv (K=4) + SiLU, strided input ----------------
__global__ __launch_bounds__(256) void conv_silu_kernel(
    const float* __restrict__ in, int inStride, int inOff,
    float* __restrict__ out, const float* __restrict__ w)
{
    int idx = blockIdx.x * 256 + threadIdx.x;
    int c   = idx & 1023;
    int tch = (idx >> 10) & 15;
    int b   = idx >> 14;
    int t0  = tch * 64;
    float w0 = w[c*4+0], w1 = w[c*4+1], w2 = w[c*4+2], w3 = w[c*4+3];
    size_t ibase = ((size_t)b * TT) * inStride + inOff + c;
    size_t obase = ((size_t)b * TT) * DD + c;
    float xm3 = (t0 >= 3) ? in[ibase + (size_t)(t0-3)*inStride] : 0.f;
    float xm2 = (t0 >= 2) ? in[ibase + (size_t)(t0-2)*inStride] : 0.f;
    float xm1 = (t0 >= 1) ? in[ibase + (size_t)(t0-1)*inStride] : 0.f;
    #pragma unroll 8
    for (int j = 0; j < 64; j++) {
        float xt = in[ibase + (size_t)(t0+j)*inStride];
        float s  = xm3*w0 + xm2*w1 + xm1*w2 + xt*w3;
        out[obase + (size_t)(t0+j)*DD] = s / (1.f + expf(-s));
        xm3 = xm2; xm2 = xm1; xm1 = xt;
    }
}

// ---------------- L2 norm of q (with scale) and k ----------------
__global__ __launch_bounds__(256) void l2norm_qk_kernel(
    float* __restrict__ qc, float* __restrict__ kc)
{
    int gw = blockIdx.x * 8 + (threadIdx.x >> 5);
    int lane = threadIdx.x & 31;
    float* arr = (gw < 65536) ? qc : kc;
    size_t base = (size_t)(gw & 65535) * 64;
    float a = arr[base + lane], b = arr[base + 32 + lane];
    float ss = a*a + b*b;
    #pragma unroll
    for (int off = 16; off; off >>= 1) ss += __shfl_xor_sync(0xffffffffu, ss, off);
    float r = rsqrtf(ss + 1e-6f);
    if (gw < 65536) r *= 0.125f;
    arr[base + lane]      = a * r;
    arr[base + 32 + lane] = b * r;
}

// ---------------- beta / gate ----------------
__global__ __launch_bounds__(256) void betag_kernel(
    const float* __restrict__ hb, const float* __restrict__ ha,
    const float* __restrict__ dtb, const float* __restrict__ Alog,
    float* __restrict__ beta, float* __restrict__ gex)
{
    int idx = blockIdx.x * 256 + threadIdx.x;
    int hh = idx & 15;
    beta[idx] = 2.f / (1.f + expf(-hb[idx]));
    float xv = ha[idx] + dtb[hh];
    float sp = (xv > 20.f) ? xv : log1pf(expf(xv));
    gex[idx] = expf(-expf(Alog[hh]) * sp);
}

// ---------------- gated delta-rule scan (8-step staging) ----------------
__global__ __launch_bounds__(256) void scan_kernel(
    const float* __restrict__ q, const float* __restrict__ k, const float* __restrict__ v,
    const float* __restrict__ beta, const float* __restrict__ gex,
    float* __restrict__ o, float* __restrict__ state)
{
    int hf   = blockIdx.x & 1;
    int h    = (blockIdx.x >> 1) & 15;
    int b    = blockIdx.x >> 5;
    int tid  = threadIdx.x, lane = tid & 31, w = tid >> 5;
    int dvL  = (w << 2) | (lane & 3);
    int dv   = hf * 32 + dvL;
    int kbase = (lane >> 2) << 3;

    __shared__ float sQ[2][8][64], sK[2][8][64], sV[2][8][32], sBe[2][8], sG[2][8];

    float S[8];
    #pragma unroll
    for (int j = 0; j < 8; j++) S[j] = 0.f;

    size_t chan = (size_t)h * 64;

    #define SCAN_LOAD(st, bf) {                                                          \
        size_t tb = (size_t)b * TT + (st) * 8;                                           \
        for (int i = tid; i < 1296; i += 256) {                                          \
            if (i < 512)       sQ[bf][i>>6][i&63] = q[(tb + (i>>6))*DD + chan + (i&63)]; \
            else if (i < 1024) { int j2 = i-512;                                         \
                sK[bf][j2>>6][j2&63] = k[(tb + (j2>>6))*DD + chan + (j2&63)]; }          \
            else if (i < 1280) { int j2 = i-1024;                                        \
                sV[bf][j2>>5][j2&31] = v[(tb + (j2>>5))*DD + chan + hf*32 + (j2&31)]; }  \
            else { int j2 = i-1280;                                                      \
                if (j2 < 8) sBe[bf][j2] = beta[(tb + j2)*HH + h];                        \
                else        sG[bf][j2-8] = gex[(tb + j2-8)*HH + h]; }                    \
        }                                                                                \
    }

    SCAN_LOAD(0, 0);

    for (int st = 0; st < 128; st++) {
        int buf = st & 1;
        __syncthreads();
        if (st + 1 < 128) SCAN_LOAD(st + 1, buf ^ 1);
        #pragma unroll 2
        for (int tt = 0; tt < 8; tt++) {
            float ge = sG[buf][tt], bt = sBe[buf][tt];
            float kv = 0.f;
            #pragma unroll
            for (int j = 0; j < 8; j++) { S[j] *= ge; kv = fmaf(sK[buf][tt][kbase+j], S[j], kv); }
            kv += __shfl_xor_sync(0xffffffffu, kv, 4);
            kv += __shfl_xor_sync(0xffffffffu, kv, 8);
            kv += __shfl_xor_sync(0xffffffffu, kv, 16);
            float delta = (sV[buf][tt][dvL] - kv) * bt;
            float ov = 0.f;
            #pragma unroll
            for (int j = 0; j < 8; j++) {
                S[j] = fmaf(sK[buf][tt][kbase+j], delta, S[j]);
                ov   = fmaf(sQ[buf][tt][kbase+j], S[j], ov);
            }
            ov += __shfl_xor_sync(0xffffffffu, ov, 4);
            ov += __shfl_xor_sync(0xffffffffu, ov, 8);
            ov += __shfl_xor_sync(0xffffffffu, ov, 16);
            if ((lane >> 2) == 0)
                o[((size_t)b * TT + st * 8 + tt) * DD + chan + dv] = ov;
        }
    }
    #pragma unroll
    for (int j = 0; j < 8; j++)
        state[(((size_t)b * HH + h) * DK + kbase + j) * DV + dv] = S[j];
}

// ---------------- host launch ----------------
extern "C" void kernel_launch(void* const* d_in, const int* in_sizes, int n_in,
                              void* d_out, int out_size)
{
    const float* x    = (const float*)d_in[0];
    const float* anw  = (const float*)d_in[1];
    const float* Wq   = (const float*)d_in[2];
    const float* Wk   = (const float*)d_in[3];
    const float* Wv   = (const float*)d_in[4];
    const float* cq   = (const float*)d_in[5];
    const float* ck   = (const float*)d_in[6];
    const float* cv   = (const float*)d_in[7];
    const float* Wb   = (const float*)d_in[8];
    const float* Wa   = (const float*)d_in[9];
    const float* dtb  = (const float*)d_in[10];
    const float* Alog = (const float*)d_in[11];
    const float* ow   = (const float*)d_in[12];
    const float* Wo   = (const float*)d_in[13];
    const float* mlpw = (const float*)d_in[14];
    const float* Wg   = (const float*)d_in[15];
    const float* Wd   = (const float*)d_in[16];
    float* out = (float*)d_out;

    float *h1,*qkv,*qc,*kc,*vc,*hb,*ha,*beta,*gex,*o,*h2,*gml,*sdump;
    __half *A2, *B2;
    cudaGetSymbolAddress((void**)&h1, g_h1);
    cudaGetSymbolAddress((void**)&qkv, g_qkv);
    cudaGetSymbolAddress((void**)&qc, g_qc);
    cudaGetSymbolAddress((void**)&kc, g_kc);
    cudaGetSymbolAddress((void**)&vc, g_vc);
    cudaGetSymbolAddress((void**)&hb, g_hb);
    cudaGetSymbolAddress((void**)&ha, g_ha);
    cudaGetSymbolAddress((void**)&beta, g_beta);
    cudaGetSymbolAddress((void**)&gex,  g_gex);
    cudaGetSymbolAddress((void**)&o,  g_o);
    cudaGetSymbolAddress((void**)&h2, g_h2);
    cudaGetSymbolAddress((void**)&gml, g_gml);
    cudaGetSymbolAddress((void**)&sdump, g_sdump);
    cudaGetSymbolAddress((void**)&A2, g_A2);
    cudaGetSymbolAddress((void**)&B2, g_B2);

    cudaFuncSetAttribute(tc_gemm, cudaFuncAttributeMaxDynamicSharedMemorySize, GSMEM);

    float* state_out = (out_size >= ROWS*DD + BB*HH*DK*DV) ? (out + (size_t)ROWS*DD) : sdump;

    // 1) pre-attn norm fused with fp16 split (keeps fp32 h1 for proj_ba)
    rmsnorm_splitA<<<ROWS, 256>>>(x, anw, h1, A2);
    // 2) fused QKV GEMM: N=3072, KB=1024
    convB_kernel<<<dim3(32, 32), 256>>>(Wq, B2, 1024, 1024, 0);
    convB_kernel<<<dim3(32, 32), 256>>>(Wk, B2, 1024, 1024, 1024);
    convB_kernel<<<dim3(32, 32), 256>>>(Wv, B2, 1024, 1024, 2048);
    tc_gemm<<<dim3(12, 32), 256, GSMEM>>>(A2, B2, nullptr, qkv, 3072, 1024);
    // 3) conv + silu, projections
    conv_silu_kernel<<<256, 256>>>(qkv, 3072, 0,    qc, cq);
    conv_silu_kernel<<<256, 256>>>(qkv, 3072, 1024, kc, ck);
    conv_silu_kernel<<<256, 256>>>(qkv, 3072, 2048, vc, cv);
    proj_ba_kernel<<<ROWS, 256>>>(h1, Wb, Wa, hb, ha);
    l2norm_qk_kernel<<<16384, 256>>>(qc, kc);
    betag_kernel<<<256, 256>>>(hb, ha, dtb, Alog, beta, gex);
    // 4) sequential delta-rule scan
    scan_kernel<<<128, 256>>>(qc, kc, vc, beta, gex, o, state_out);
    // 5) per-head norm fused with split; h2 = x + o' @ Wo
    ornorm_splitA<<<ROWS, 256>>>(o, ow, A2);
    convB_kernel<<<dim3(32, 32), 256>>>(Wo, B2, 1024, 1024, 0);
    tc_gemm<<<dim3(4, 32), 256, GSMEM>>>(A2, B2, x, h2, 1024, 1024);
    // 6) MLP
    rmsnorm_splitA<<<ROWS, 256>>>(h2, mlpw, nullptr, A2);
    convB_kernel<<<dim3(176, 32), 256>>>(Wg, B2, 1024, 5632, 0);
    tc_gemm<<<dim3(22, 32), 256, GSMEM>>>(A2, B2, nullptr, gml, 5632, 1024);
    swiglu_splitA<<<dim3(11, ROWS), 256>>>(gml, A2);
    convB_kernel<<<dim3(32, 88), 256>>>(Wd, B2, 2816, 1024, 0);
    tc_gemm<<<dim3(4, 32), 256, GSMEM>>>(A2, B2, h2, out, 1024, 2816);
}

// round 8
// speedup vs baseline: 1.0701x; 1.0672x over previous
#include <cuda_runtime.h>
#include <cuda_fp16.h>
#include <cstdint>

// ---------------- problem constants ----------------
#define BB 4
#define TT 1024
#define DD 1024
#define HH 16
#define DK 64
#define DV 64
#define II 2816
#define ROWS (BB*TT)          // 4096

// B2 region offsets (halfs)
#define OFF_QKV 0
#define OFF_O   (3072*1024)
#define OFF_G   (OFF_O + 1024*1024)
#define OFF_D   (OFF_G + 5632*1024)
#define B2_TOTAL (OFF_D + 1024*2816)

// ---------------- scratch (device globals; no runtime alloc) ----------------
__device__ float g_h1[ROWS*DD];
__device__ float g_qkv[(size_t)ROWS*3*DD];
__device__ float g_qc[ROWS*DD];
__device__ float g_kc[ROWS*DD];
__device__ float g_vc[ROWS*DD];
__device__ float g_hb[ROWS*HH];
__device__ float g_ha[ROWS*HH];
__device__ float g_beta[ROWS*HH];
__device__ float g_gex[ROWS*HH];
__device__ float g_o [ROWS*DD];
__device__ float g_h2[ROWS*DD];
__device__ float g_gml[(size_t)ROWS*2*II];
__device__ float g_sdump[BB*HH*DK*DV];
__device__ __half g_A2[(size_t)ROWS*2*II];       // [hi|lo] rows, max KX=5632
__device__ __half g_B2[(size_t)B2_TOTAL];        // all weights fp16, [N,K] each

// ================= helpers =================
__device__ __forceinline__ uint32_t smem_u32(const void* p) {
    uint32_t a;
    asm("{ .reg .u64 t; cvta.to.shared.u64 t, %1; cvt.u32.u64 %0, t; }" : "=r"(a) : "l"(p));
    return a;
}
__device__ __forceinline__ void cp16(uint32_t dst, const void* src) {
    asm volatile("cp.async.cg.shared.global [%0], [%1], 16;" :: "r"(dst), "l"(src) : "memory");
}
__device__ __forceinline__ void ldm_x4(uint32_t* r, uint32_t a) {
    asm volatile("ldmatrix.sync.aligned.m8n8.x4.shared.b16 {%0,%1,%2,%3}, [%4];"
                 : "=r"(r[0]), "=r"(r[1]), "=r"(r[2]), "=r"(r[3]) : "r"(a));
}
__device__ __forceinline__ void mma_f16(float* c, const uint32_t* a, const uint32_t* b) {
    asm volatile(
        "mma.sync.aligned.m16n8k16.row.col.f32.f16.f16.f32 "
        "{%0,%1,%2,%3}, {%4,%5,%6,%7}, {%8,%9}, {%0,%1,%2,%3};"
        : "+f"(c[0]), "+f"(c[1]), "+f"(c[2]), "+f"(c[3])
        : "r"(a[0]), "r"(a[1]), "r"(a[2]), "r"(a[3]), "r"(b[0]), "r"(b[1]));
}
__device__ __forceinline__ void split2(float x, __half& hi, __half& lo) {
    hi = __float2half_rn(x);
    lo = __float2half_rn(x - __half2float(hi));
}

// ================= fp16 HMMA GEMM (R4 shape + single-copy B k-wrap) =================
// C[4096,Nfull] = A2[M, 2*KB] * Bw[N, KB]^T (+Add); A2 rows = [hi | lo]; B k-index wraps mod KB.
// CTA 128x128, 4 warps (2x2 of 64x64), BK=64, 3-stage cp.async, 2 CTAs/SM.
#define STG_BYTES 32768
#define GSMEM (3*STG_BYTES)    // 96 KB

__global__ void __launch_bounds__(128, 2)
tc_gemm(const __half* __restrict__ A, const __half* __restrict__ B,
        const float* __restrict__ Add, float* __restrict__ C, int Nfull, int KB)
{
    extern __shared__ __align__(1024) char smem[];
    uint32_t sb = smem_u32(smem);
    const int tid = threadIdx.x;
    const int lane = tid & 31, w = tid >> 5;
    const int wm = w & 1, wn = w >> 1;
    const int m0 = blockIdx.y * 128, n0 = blockIdx.x * 128;
    const int KX = 2 * KB;
    const int NK = KX >> 6;

    const __half* Ab = A + (size_t)m0 * KX;
    const __half* Bb = B + (size_t)n0 * KB;

    const int cr = tid >> 3, cc = tid & 7;       // cr 0..15
    const uint32_t cdst = (uint32_t)(cr * 128 + ((cc ^ (cr & 7)) << 4));

    float acc[4][8][4];
    #pragma unroll
    for (int i = 0; i < 4; i++)
        #pragma unroll
        for (int j = 0; j < 8; j++)
            #pragma unroll
            for (int l = 0; l < 4; l++) acc[i][j][l] = 0.f;

    const int rowA = wm * 64 + (lane & 15);
    const int rowB = wn * 64 + (lane & 7) + ((lane >> 4) << 3);
    uint32_t aChunk[4], bChunk[4];
    #pragma unroll
    for (int ks = 0; ks < 4; ks++) {
        aChunk[ks] = (uint32_t)(((ks * 2 + (lane >> 4)) ^ (rowA & 7)) << 4);
        bChunk[ks] = (uint32_t)(((ks * 2 + ((lane >> 3) & 1)) ^ (rowB & 7)) << 4);
    }

    #define LOAD_STAGE(kt, s) {                                                   \
        uint32_t sa = sb + (s) * STG_BYTES, sbB = sa + 16384;                      \
        int kA = (kt) * 64;                                                        \
        int kB = (kA >= KB) ? kA - KB : kA;                                        \
        const __half* Asrc = Ab + (size_t)cr * KX + kA + cc * 8;                   \
        const __half* Bsrc = Bb + (size_t)cr * KB + kB + cc * 8;                   \
        _Pragma("unroll")                                                          \
        for (int t = 0; t < 8; t++) {                                              \
            cp16(sa  + cdst + t * 2048, Asrc + (size_t)(t * 16) * KX);             \
            cp16(sbB + cdst + t * 2048, Bsrc + (size_t)(t * 16) * KB);             \
        }                                                                          \
        asm volatile("cp.async.commit_group;" ::: "memory");                       \
    }

    LOAD_STAGE(0, 0);
    LOAD_STAGE(1, 1);

    for (int kt = 0; kt < NK; kt++) {
        int s = kt - (kt / 3) * 3;
        asm volatile("cp.async.wait_group 1;" ::: "memory");
        __syncthreads();
        if (kt + 2 < NK) {
            int s2 = (kt + 2) - ((kt + 2) / 3) * 3;
            LOAD_STAGE(kt + 2, s2);
        } else {
            asm volatile("cp.async.commit_group;" ::: "memory");
        }
        uint32_t sa = sb + s * STG_BYTES, sbB = sa + 16384;
        uint32_t baseA = sa + (uint32_t)rowA * 128;
        uint32_t baseB = sbB + (uint32_t)rowB * 128;
        #pragma unroll
        for (int ks = 0; ks < 4; ks++) {
            uint32_t a[4][4], b[8][2];
            #pragma unroll
            for (int mt = 0; mt < 4; mt++)
                ldm_x4(a[mt], baseA + mt * 2048 + aChunk[ks]);
            #pragma unroll
            for (int np = 0; np < 4; np++) {
                uint32_t r[4];
                ldm_x4(r, baseB + np * 2048 + bChunk[ks]);
                b[2*np][0] = r[0]; b[2*np][1] = r[1];
                b[2*np+1][0] = r[2]; b[2*np+1][1] = r[3];
            }
            #pragma unroll
            for (int mt = 0; mt < 4; mt++)
                #pragma unroll
                for (int nt = 0; nt < 8; nt++)
                    mma_f16(acc[mt][nt], a[mt], b[nt]);
        }
        __syncthreads();
    }

    // ---- epilogue ----
    const int l4 = lane >> 2, l2 = (lane & 3) * 2;
    #pragma unroll
    for (int mt = 0; mt < 4; mt++) {
        size_t r0 = (size_t)(m0 + wm * 64 + mt * 16 + l4);
        #pragma unroll
        for (int nt = 0; nt < 8; nt++) {
            size_t cidx = r0 * Nfull + (n0 + wn * 64 + nt * 8 + l2);
            float2 v0 = make_float2(acc[mt][nt][0], acc[mt][nt][1]);
            float2 v1 = make_float2(acc[mt][nt][2], acc[mt][nt][3]);
            if (Add) {
                float2 a0 = *(const float2*)(Add + cidx);
                float2 a1 = *(const float2*)(Add + cidx + 8 * Nfull);
                v0.x += a0.x; v0.y += a0.y; v1.x += a1.x; v1.y += a1.y;
            }
            *(float2*)(C + cidx) = v0;
            *(float2*)(C + cidx + 8 * Nfull) = v1;
        }
    }
}

// ================= fused norm + fp16 split (A-operand) =================
__global__ __launch_bounds__(256) void rmsnorm_splitA(
    const float* __restrict__ in, const float* __restrict__ w,
    float* __restrict__ hout, __half* __restrict__ A2)
{
    int row = blockIdx.x;
    __shared__ float red[8];
    const float* p = in + (size_t)row * DD;
    float v0 = p[threadIdx.x];
    float v1 = p[threadIdx.x + 256];
    float v2 = p[threadIdx.x + 512];
    float v3 = p[threadIdx.x + 768];
    float ss = v0*v0 + v1*v1 + v2*v2 + v3*v3;
    #pragma unroll
    for (int off = 16; off; off >>= 1) ss += __shfl_xor_sync(0xffffffffu, ss, off);
    if ((threadIdx.x & 31) == 0) red[threadIdx.x >> 5] = ss;
    __syncthreads();
    float tot = 0.f;
    #pragma unroll
    for (int i = 0; i < 8; i++) tot += red[i];
    float r = rsqrtf(tot * (1.0f/1024.0f) + 1e-6f);
    __half* a = A2 + (size_t)row * 2048;
    float* q = hout ? hout + (size_t)row * DD : nullptr;
    float vals[4] = {v0, v1, v2, v3};
    #pragma unroll
    for (int i = 0; i < 4; i++) {
        int c = threadIdx.x + i * 256;
        float val = vals[i] * r * w[c];
        if (q) q[c] = val;
        __half hi, lo; split2(val, hi, lo);
        a[c] = hi; a[1024 + c] = lo;
    }
}

__global__ __launch_bounds__(256) void ornorm_splitA(
    const float* __restrict__ o, const float* __restrict__ w, __half* __restrict__ A2)
{
    int row = blockIdx.x, t = threadIdx.x;
    float4 vv = *(const float4*)(o + (size_t)row * 1024 + t * 4);
    float ss = vv.x*vv.x + vv.y*vv.y + vv.z*vv.z + vv.w*vv.w;
    ss += __shfl_xor_sync(0xffffffffu, ss, 1);
    ss += __shfl_xor_sync(0xffffffffu, ss, 2);
    ss += __shfl_xor_sync(0xffffffffu, ss, 4);
    ss += __shfl_xor_sync(0xffffffffu, ss, 8);
    float r = rsqrtf(ss * (1.0f/64.0f) + 1e-6f);
    __half* a = A2 + (size_t)row * 2048;
    float vals[4] = {vv.x, vv.y, vv.z, vv.w};
    #pragma unroll
    for (int j = 0; j < 4; j++) {
        int c = t * 4 + j;
        float val = vals[j] * r * w[c & 63];
        __half hi, lo; split2(val, hi, lo);
        a[c] = hi; a[1024 + c] = lo;
    }
}

__global__ __launch_bounds__(256) void swiglu_splitA(
    const float* __restrict__ gml, __half* __restrict__ A2)
{
    int col = blockIdx.x * 256 + threadIdx.x;
    int row = blockIdx.y;
    float g = gml[(size_t)row * 5632 + col];
    float y = gml[(size_t)row * 5632 + 2816 + col];
    float m = g / (1.f + expf(-g)) * y;
    __half hi, lo; split2(m, hi, lo);
    A2[(size_t)row * 5632 + col] = hi;
    A2[(size_t)row * 5632 + 2816 + col] = lo;
}

// W[K,N] -> B2[n][k] fp16 (transposed, single copy)
__global__ __launch_bounds__(256) void convB_kernel(
    const float* __restrict__ W, __half* __restrict__ B2, int K, int N)
{
    __shared__ float tile[32][33];
    int k0 = blockIdx.y * 32, n0 = blockIdx.x * 32;
    int tx = threadIdx.x & 31, ty = threadIdx.x >> 5;
    for (int i = ty; i < 32; i += 8)
        tile[i][tx] = W[(size_t)(k0 + i) * N + n0 + tx];
    __syncthreads();
    for (int i = ty; i < 32; i += 8) {
        size_t rb = (size_t)(n0 + i) * K;
        B2[rb + k0 + tx] = __float2half_rn(tile[tx][i]);
    }
}

// merged Wq/Wk/Wv conversion (z selects matrix)
__global__ __launch_bounds__(256) void convB_qkv_kernel(
    const float* __restrict__ Wq, const float* __restrict__ Wk, const float* __restrict__ Wv,
    __half* __restrict__ B2)
{
    const float* W = (blockIdx.z == 0) ? Wq : (blockIdx.z == 1) ? Wk : Wv;
    __shared__ float tile[32][33];
    int k0 = blockIdx.y * 32, n0 = blockIdx.x * 32;
    int tx = threadIdx.x & 31, ty = threadIdx.x >> 5;
    for (int i = ty; i < 32; i += 8)
        tile[i][tx] = W[(size_t)(k0 + i) * 1024 + n0 + tx];
    __syncthreads();
    for (int i = ty; i < 32; i += 8) {
        size_t rb = (size_t)(blockIdx.z * 1024 + n0 + i) * 1024;
        B2[rb + k0 + tx] = __float2half_rn(tile[tx][i]);
    }
}

// ---------------- small projections ----------------
__global__ __launch_bounds__(256) void proj_ba_kernel(
    const float* __restrict__ h, const float* __restrict__ Wb, const float* __restrict__ Wa,
    float* __restrict__ hb, float* __restrict__ ha)
{
    int row = blockIdx.x;
    __shared__ float sh[1024];
    for (int i = threadIdx.x; i < 1024; i += 256) sh[i] = h[(size_t)row * DD + i];
    __syncthreads();
    int grp = threadIdx.x >> 3, l = threadIdx.x & 7;
    const float* W = (grp < 16) ? Wb : Wa;
    int col = grp & 15;
    float s = 0.f;
    for (int k = l; k < 1024; k += 8) s += sh[k] * W[k * HH + col];
    s += __shfl_xor_sync(0xffffffffu, s, 1);
    s += __shfl_xor_sync(0xffffffffu, s, 2);
    s += __shfl_xor_sync(0xffffffffu, s, 4);
    if (l == 0) {
        if (grp < 16) hb[(size_t)row * HH + col] = s;
        else          ha[(size_t)row * HH + col] = s;
    }
}

// ---------------- causal depthwise conv (K=4) + SiLU, all three in one ----------------
__global__ __launch_bounds__(256) void conv_silu3_kernel(
    const float* __restrict__ qkv,
    float* __restrict__ qc, float* __restrict__ kc, float* __restrict__ vc,
    const float* __restrict__ cq, const float* __restrict__ ck, const float* __restrict__ cv)
{
    int which = blockIdx.y;                         // 0=q 1=k 2=v
    const float* w = (which == 0) ? cq : (which == 1) ? ck : cv;
    float* out = (which == 0) ? qc : (which == 1) ? kc : vc;
    int inOff = which * 1024;

    int idx = blockIdx.x * 256 + threadIdx.x;
    int c   = idx & 1023;
    int tch = (idx >> 10) & 15;
    int b   = idx >> 14;
    int t0  = tch * 64;
    float w0 = w[c*4+0], w1 = w[c*4+1], w2 = w[c*4+2], w3 = w[c*4+3];
    size_t ibase = ((size_t)b * TT) * 3072 + inOff + c;
    size_t obase = ((size_t)b * TT) * DD + c;
    float xm3 = (t0 >= 3) ? qkv[ibase + (size_t)(t0-3)*3072] : 0.f;
    float xm2 = (t0 >= 2) ? qkv[ibase + (size_t)(t0-2)*3072] : 0.f;
    float xm1 = (t0 >= 1) ? qkv[ibase + (size_t)(t0-1)*3072] : 0.f;
    #pragma unroll 8
    for (int j = 0; j < 64; j++) {
        float xt = qkv[ibase + (size_t)(t0+j)*3072];
        float s  = xm3*w0 + xm2*w1 + xm1*w2 + xt*w3;
        out[obase + (size_t)(t0+j)*DD] = s / (1.f + expf(-s));
        xm3 = xm2; xm2 = xm1; xm1 = xt;
    }
}

// ---------------- L2 norm of q (with scale) and k ----------------
__global__ __launch_bounds__(256) void l2norm_qk_kernel(
    float* __restrict__ qc, float* __restrict__ kc)
{
    int gw = blockIdx.x * 8 + (threadIdx.x >> 5);
    int lane = threadIdx.x & 31;
    float* arr = (gw < 65536) ? qc : kc;
    size_t base = (size_t)(gw & 65535) * 64;
    float a = arr[base + lane], b = arr[base + 32 + lane];
    float ss = a*a + b*b;
    #pragma unroll
    for (int off = 16; off; off >>= 1) ss += __shfl_xor_sync(0xffffffffu, ss, off);
    float r = rsqrtf(ss + 1e-6f);
    if (gw < 65536) r *= 0.125f;
    arr[base + lane]      = a * r;
    arr[base + 32 + lane] = b * r;
}

// ---------------- beta / gate ----------------
__global__ __launch_bounds__(256) void betag_kernel(
    const float* __restrict__ hb, const float* __restrict__ ha,
    const float* __restrict__ dtb, const float* __restrict__ Alog,
    float* __restrict__ beta, float* __restrict__ gex)
{
    int idx = blockIdx.x * 256 + threadIdx.x;
    int hh = idx & 15;
    beta[idx] = 2.f / (1.f + expf(-hb[idx]));
    float xv = ha[idx] + dtb[hh];
    float sp = (xv > 20.f) ? xv : log1pf(expf(xv));
    gex[idx] = expf(-expf(Alog[hh]) * sp);
}

// ---------------- gated delta-rule scan (8-step staging) ----------------
__global__ __launch_bounds__(256) void scan_kernel(
    const float* __restrict__ q, const float* __restrict__ k, const float* __restrict__ v,
    const float* __restrict__ beta, const float* __restrict__ gex,
    float* __restrict__ o, float* __restrict__ state)
{
    int hf   = blockIdx.x & 1;
    int h    = (blockIdx.x >> 1) & 15;
    int b    = blockIdx.x >> 5;
    int tid  = threadIdx.x, lane = tid & 31, w = tid >> 5;
    int dvL  = (w << 2) | (lane & 3);
    int dv   = hf * 32 + dvL;
    int kbase = (lane >> 2) << 3;

    __shared__ float sQ[2][8][64], sK[2][8][64], sV[2][8][32], sBe[2][8], sG[2][8];

    float S[8];
    #pragma unroll
    for (int j = 0; j < 8; j++) S[j] = 0.f;

    size_t chan = (size_t)h * 64;

    #define SCAN_LOAD(st, bf) {                                                          \
        size_t tb = (size_t)b * TT + (st) * 8;                                           \
        for (int i = tid; i < 1296; i += 256) {                                          \
            if (i < 512)       sQ[bf][i>>6][i&63] = q[(tb + (i>>6))*DD + chan + (i&63)]; \
            else if (i < 1024) { int j2 = i-512;                                         \
                sK[bf][j2>>6][j2&63] = k[(tb + (j2>>6))*DD + chan + (j2&63)]; }          \
            else if (i < 1280) { int j2 = i-1024;                                        \
                sV[bf][j2>>5][j2&31] = v[(tb + (j2>>5))*DD + chan + hf*32 + (j2&31)]; }  \
            else { int j2 = i-1280;                                                      \
                if (j2 < 8) sBe[bf][j2] = beta[(tb + j2)*HH + h];                        \
                else        sG[bf][j2-8] = gex[(tb + j2-8)*HH + h]; }                    \
        }                                                                                \
    }

    SCAN_LOAD(0, 0);

    for (int st = 0; st < 128; st++) {
        int buf = st & 1;
        __syncthreads();
        if (st + 1 < 128) SCAN_LOAD(st + 1, buf ^ 1);
        #pragma unroll 2
        for (int tt = 0; tt < 8; tt++) {
            float ge = sG[buf][tt], bt = sBe[buf][tt];
            float kv = 0.f;
            #pragma unroll
            for (int j = 0; j < 8; j++) { S[j] *= ge; kv = fmaf(sK[buf][tt][kbase+j], S[j], kv); }
            kv += __shfl_xor_sync(0xffffffffu, kv, 4);
            kv += __shfl_xor_sync(0xffffffffu, kv, 8);
            kv += __shfl_xor_sync(0xffffffffu, kv, 16);
            float delta = (sV[buf][tt][dvL] - kv) * bt;
            float ov = 0.f;
            #pragma unroll
            for (int j = 0; j < 8; j++) {
                S[j] = fmaf(sK[buf][tt][kbase+j], delta, S[j]);
                ov   = fmaf(sQ[buf][tt][kbase+j], S[j], ov);
            }
            ov += __shfl_xor_sync(0xffffffffu, ov, 4);
            ov += __shfl_xor_sync(0xffffffffu, ov, 8);
            ov += __shfl_xor_sync(0xffffffffu, ov, 16);
            if ((lane >> 2) == 0)
                o[((size_t)b * TT + st * 8 + tt) * DD + chan + dv] = ov;
        }
    }
    #pragma unroll
    for (int j = 0; j < 8; j++)
        state[(((size_t)b * HH + h) * DK + kbase + j) * DV + dv] = S[j];
}

// ---------------- host launch ----------------
extern "C" void kernel_launch(void* const* d_in, const int* in_sizes, int n_in,
                              void* d_out, int out_size)
{
    const float* x    = (const float*)d_in[0];
    const float* anw  = (const float*)d_in[1];
    const float* Wq   = (const float*)d_in[2];
    const float* Wk   = (const float*)d_in[3];
    const float* Wv   = (const float*)d_in[4];
    const float* cq   = (const float*)d_in[5];
    const float* ck   = (const float*)d_in[6];
    const float* cv   = (const float*)d_in[7];
    const float* Wb   = (const float*)d_in[8];
    const float* Wa   = (const float*)d_in[9];
    const float* dtb  = (const float*)d_in[10];
    const float* Alog = (const float*)d_in[11];
    const float* ow   = (const float*)d_in[12];
    const float* Wo   = (const float*)d_in[13];
    const float* mlpw = (const float*)d_in[14];
    const float* Wg   = (const float*)d_in[15];
    const float* Wd   = (const float*)d_in[16];
    float* out = (float*)d_out;

    float *h1,*qkv,*qc,*kc,*vc,*hb,*ha,*beta,*gex,*o,*h2,*gml,*sdump;
    __half *A2, *B2;
    cudaGetSymbolAddress((void**)&h1, g_h1);
    cudaGetSymbolAddress((void**)&qkv, g_qkv);
    cudaGetSymbolAddress((void**)&qc, g_qc);
    cudaGetSymbolAddress((void**)&kc, g_kc);
    cudaGetSymbolAddress((void**)&vc, g_vc);
    cudaGetSymbolAddress((void**)&hb, g_hb);
    cudaGetSymbolAddress((void**)&ha, g_ha);
    cudaGetSymbolAddress((void**)&beta, g_beta);
    cudaGetSymbolAddress((void**)&gex,  g_gex);
    cudaGetSymbolAddress((void**)&o,  g_o);
    cudaGetSymbolAddress((void**)&h2, g_h2);
    cudaGetSymbolAddress((void**)&gml, g_gml);
    cudaGetSymbolAddress((void**)&sdump, g_sdump);
    cudaGetSymbolAddress((void**)&A2, g_A2);
    cudaGetSymbolAddress((void**)&B2, g_B2);

    cudaFuncSetAttribute(tc_gemm, cudaFuncAttributeMaxDynamicSharedMemorySize, GSMEM);

    float* state_out = (out_size >= ROWS*DD + BB*HH*DK*DV) ? (out + (size_t)ROWS*DD) : sdump;

    // ---- weight conversions up-front (launches 0-3) ----
    convB_qkv_kernel<<<dim3(32, 32, 3), 256>>>(Wq, Wk, Wv, B2 + OFF_QKV);
    convB_kernel<<<dim3(32, 32), 256>>>(Wo, B2 + OFF_O, 1024, 1024);
    convB_kernel<<<dim3(176, 32), 256>>>(Wg, B2 + OFF_G, 1024, 5632);
    convB_kernel<<<dim3(32, 88), 256>>>(Wd, B2 + OFF_D, 2816, 1024);
    // ---- [4] pre-attn norm + split ----
    rmsnorm_splitA<<<ROWS, 256>>>(x, anw, h1, A2);
    // ---- [5] QKV GEMM (profiled slot): N=3072, KB=1024 ----
    tc_gemm<<<dim3(24, 32), 128, GSMEM>>>(A2, B2 + OFF_QKV, nullptr, qkv, 3072, 1024);
    // ---- conv + silu, projections ----
    conv_silu3_kernel<<<dim3(256, 3), 256>>>(qkv, qc, kc, vc, cq, ck, cv);
    proj_ba_kernel<<<ROWS, 256>>>(h1, Wb, Wa, hb, ha);
    l2norm_qk_kernel<<<16384, 256>>>(qc, kc);
    betag_kernel<<<256, 256>>>(hb, ha, dtb, Alog, beta, gex);
    // ---- scan ----
    scan_kernel<<<128, 256>>>(qc, kc, vc, beta, gex, o, state_out);
    // ---- h2 = x + o' @ Wo ----
    ornorm_splitA<<<ROWS, 256>>>(o, ow, A2);
    tc_gemm<<<dim3(8, 32), 128, GSMEM>>>(A2, B2 + OFF_O, x, h2, 1024, 1024);
    // ---- MLP ----
    rmsnorm_splitA<<<ROWS, 256>>>(h2, mlpw, nullptr, A2);
    tc_gemm<<<dim3(44, 32), 128, GSMEM>>>(A2, B2 + OFF_G, nullptr, gml, 5632, 1024);
    swiglu_splitA<<<dim3(11, ROWS), 256>>>(gml, A2);
    tc_gemm<<<dim3(8, 32), 128, GSMEM>>>(A2, B2 + OFF_D, h2, out, 1024, 2816);
}